// round 8
// baseline (speedup 1.0000x reference)
#include <cuda_runtime.h>
#include <cuda_bf16.h>
#include <math.h>
#include <stdint.h>

// DeepFM fused, bf16 mma.sync, 2 CTAs/SM (BM=64, TPB=256).
#define BB   16384
#define FF   26
#define VV   100000
#define DD   16
#define K1   416      // F*D
#define HH1  256
#define HH2  128
#define EPSV 1e-5f

#define BM   64       // samples per block
#define TPB  256
#define NS1  (K1/16)  // 26 k-steps GEMM1
#define NS2  (HH1/16) // 16 k-steps GEMM2

#define AW   212      // A row pad (words): 212%32=20 -> conflict-free frag loads
#define H1W  132      // H1 row pad (words): 132%32=4 -> conflict-free
#define STW  12       // weight stage row (words): conflict-free b-frag loads

// Folded transposed bf16 weights (device-global scratch; allocation-free).
__device__ __nv_bfloat16 g_W1t[HH1 * K1];   // [n=256][k=416]
__device__ __nv_bfloat16 g_W2t[HH2 * HH1];  // [n=128][k=256]
__device__ float g_b1f[HH1];
__device__ float g_b2f[HH2];

__global__ void deepfm_fold_kernel(
    const float* __restrict__ W1, const float* __restrict__ b1,
    const float* __restrict__ g1, const float* __restrict__ be1,
    const float* __restrict__ m1, const float* __restrict__ v1,
    const float* __restrict__ W2, const float* __restrict__ b2,
    const float* __restrict__ g2, const float* __restrict__ be2,
    const float* __restrict__ m2, const float* __restrict__ v2)
{
    int i = blockIdx.x * blockDim.x + threadIdx.x;
    const int N1 = HH1 * K1;     // 106496
    const int N2 = HH2 * HH1;    // 32768
    for (int idx = i; idx < N1 + N2; idx += gridDim.x * blockDim.x) {
        if (idx < N1) {
            int n = idx / K1, k = idx - n * K1;
            float sc = g1[n] * rsqrtf(v1[n] + EPSV);
            g_W1t[idx] = __float2bfloat16_rn(W1[k * HH1 + n] * sc);
        } else {
            int t2 = idx - N1;
            int n = t2 >> 8, k = t2 & 255;
            float sc = g2[n] * rsqrtf(v2[n] + EPSV);
            g_W2t[t2] = __float2bfloat16_rn(W2[k * HH2 + n] * sc);
        }
    }
    if (i < HH1) {
        float sc = g1[i] * rsqrtf(v1[i] + EPSV);
        g_b1f[i] = be1[i] + (b1[i] - m1[i]) * sc;
    }
    if (i < HH2) {
        float sc = g2[i] * rsqrtf(v2[i] + EPSV);
        g_b2f[i] = be2[i] + (b2[i] - m2[i]) * sc;
    }
}

// smem byte offsets (H1 aliases A: A dead after GEMM1 mainloop's last barrier)
#define OFF_A    0                                   // 64*212*4 = 54272
#define OFF_ST   54272                               // 2*256*12*4 = 24576
#define OFF_B1F  (OFF_ST + 24576)                    // 1024
#define OFF_B2F  (OFF_B1F + 1024)                    // 512
#define OFF_W3   (OFF_B2F + 512)                     // 512
#define OFF_FM   (OFF_W3 + 512)                      // 256
#define OFF_LG   (OFF_FM + 256)                      // 64*2*4 = 512
#define SMEM_BYTES (OFF_LG + 512)                    // 81664

__device__ __forceinline__ void mma_bf16(float c[4], uint32_t a0, uint32_t a1,
                                         uint32_t a2, uint32_t a3,
                                         uint32_t b0, uint32_t b1)
{
    asm volatile(
        "mma.sync.aligned.m16n8k16.row.col.f32.bf16.bf16.f32 "
        "{%0,%1,%2,%3}, {%4,%5,%6,%7}, {%8,%9}, {%0,%1,%2,%3};"
        : "+f"(c[0]), "+f"(c[1]), "+f"(c[2]), "+f"(c[3])
        : "r"(a0), "r"(a1), "r"(a2), "r"(a3), "r"(b0), "r"(b1));
}

__global__ void __launch_bounds__(TPB, 2) deepfm_main_kernel(
    const int*   __restrict__ X,
    const float* __restrict__ emb1,
    const float* __restrict__ emb2,
    const float* __restrict__ W3,
    const float* __restrict__ b3,
    float*       __restrict__ out)
{
    extern __shared__ char smem[];
    uint32_t* Aw   = (uint32_t*)(smem + OFF_A);    // bf16x2 words, row stride AW
    uint32_t* H1w  = Aw;                           // alias; row stride H1W
    uint32_t* Stw  = (uint32_t*)(smem + OFF_ST);   // 2 bufs of 256*STW words
    float* b1f_s = (float*)(smem + OFF_B1F);
    float* b2f_s = (float*)(smem + OFF_B2F);
    float* w3_s  = (float*)(smem + OFF_W3);
    float* fm_s  = (float*)(smem + OFF_FM);
    float* lg_s  = (float*)(smem + OFF_LG);

    const int t    = threadIdx.x;
    const int wid  = t >> 5;       // 0..7
    const int lane = t & 31;
    const int g    = lane >> 2;    // 0..7
    const int tig  = lane & 3;     // 0..3
    const int m0   = blockIdx.x * BM;

    // ---- stage small vectors (256 threads: b1f gets all, others strided) ----
    if (t < HH1) b1f_s[t] = g_b1f[t];
    if (t < HH2) b2f_s[t] = g_b2f[t];
    else if (t < 2 * HH2) w3_s[t - HH2] = W3[t - HH2];

    // ---- gather embeddings -> bf16 A_s [m][k] (k = f*16+d) ----
    for (int r = t; r < FF * BM; r += TPB) {
        int m = r & (BM - 1);
        int f = r >> 6;
        int idx = X[(m0 + m) * FF + f];
        const float4* src = (const float4*)(emb2 + ((long)f * VV + idx) * DD);
        float4 v0 = src[0], v1 = src[1], v2 = src[2], v3 = src[3];
        uint32_t* dst = Aw + m * AW + f * 8;
        __nv_bfloat162 p;
        p = __floats2bfloat162_rn(v0.x, v0.y); dst[0] = *(uint32_t*)&p;
        p = __floats2bfloat162_rn(v0.z, v0.w); dst[1] = *(uint32_t*)&p;
        p = __floats2bfloat162_rn(v1.x, v1.y); dst[2] = *(uint32_t*)&p;
        p = __floats2bfloat162_rn(v1.z, v1.w); dst[3] = *(uint32_t*)&p;
        p = __floats2bfloat162_rn(v2.x, v2.y); dst[4] = *(uint32_t*)&p;
        p = __floats2bfloat162_rn(v2.z, v2.w); dst[5] = *(uint32_t*)&p;
        p = __floats2bfloat162_rn(v3.x, v3.y); dst[6] = *(uint32_t*)&p;
        p = __floats2bfloat162_rn(v3.z, v3.w); dst[7] = *(uint32_t*)&p;
    }
    __syncthreads();

    // ---- FM (threads 0..63, one sample each; fp32 from bf16 tile) ----
    if (t < BM) {
        float sd[DD], ssd[DD];
        #pragma unroll
        for (int d = 0; d < DD; d++) { sd[d] = 0.f; ssd[d] = 0.f; }
        const uint32_t* row = Aw + t * AW;
        #pragma unroll
        for (int f = 0; f < FF; f++) {
            #pragma unroll
            for (int w = 0; w < 8; w++) {
                uint32_t u = row[f * 8 + w];
                __nv_bfloat162 p = *(__nv_bfloat162*)&u;
                float x0 = __low2float(p), x1 = __high2float(p);
                sd[2 * w]     += x0;  ssd[2 * w]     += x0 * x0;
                sd[2 * w + 1] += x1;  ssd[2 * w + 1] += x1 * x1;
            }
        }
        float fm2 = 0.f;
        #pragma unroll
        for (int d = 0; d < DD; d++) fm2 += sd[d] * sd[d] - ssd[d];
        float fm1 = 0.f;
        #pragma unroll
        for (int f = 0; f < FF; f++)
            fm1 += emb1[f * VV + X[(m0 + t) * FF + f]];
        fm_s[t] = fm1 + 0.5f * fm2;
    }

    // Save a copy of the A-row for the H1 epilogue hazard? Not needed:
    // all A reads (FM + GEMM1 frags) complete before GEMM1's final barrier;
    // H1 writes happen after it.

    // =========================== GEMM1 ===========================
    // C[64x256] = A[64x416] @ W1t^T.  8 warps = 4 m-strips(16) x 2 n-strips(128).
    float h1v[16][4];   // keep epilogue values in regs until after barrier
    {
        const int mb = (wid >> 1) * 16;
        const int nb = (wid & 1) * 128;
        float c[16][4];
        #pragma unroll
        for (int j = 0; j < 16; j++)
            #pragma unroll
            for (int q = 0; q < 4; q++) c[j][q] = 0.f;

        // staging: thread t owns weight row t; 2x uint4 per chunk
        {
            uint4 w0 = *(const uint4*)(g_W1t + t * K1 + 0);
            uint4 w1 = *(const uint4*)(g_W1t + t * K1 + 8);
            *(uint4*)((char*)Stw + t * 48)      = w0;
            *(uint4*)((char*)Stw + t * 48 + 16) = w1;
        }
        __syncthreads();
        uint4 pf0 = *(const uint4*)(g_W1t + t * K1 + 16);
        uint4 pf1 = *(const uint4*)(g_W1t + t * K1 + 24);

        for (int ks = 0; ks < NS1; ks++) {
            const uint32_t* buf = Stw + (ks & 1) * 3072;
            const int k0w = ks * 8;
            uint32_t a0 = Aw[(mb + g)     * AW + k0w + tig];
            uint32_t a1 = Aw[(mb + g + 8) * AW + k0w + tig];
            uint32_t a2 = Aw[(mb + g)     * AW + k0w + 4 + tig];
            uint32_t a3 = Aw[(mb + g + 8) * AW + k0w + 4 + tig];
            #pragma unroll
            for (int j = 0; j < 16; j++) {
                int n = nb + j * 8 + g;
                uint32_t b0 = buf[n * STW + tig];
                uint32_t b1 = buf[n * STW + 4 + tig];
                mma_bf16(c[j], a0, a1, a2, a3, b0, b1);
            }
            if (ks + 1 < NS1) {
                char* dst = (char*)Stw + ((ks + 1) & 1) * 12288 + t * 48;
                *(uint4*)dst        = pf0;
                *(uint4*)(dst + 16) = pf1;
            }
            __syncthreads();
            if (ks + 2 < NS1) {
                pf0 = *(const uint4*)(g_W1t + t * K1 + (ks + 2) * 16);
                pf1 = *(const uint4*)(g_W1t + t * K1 + (ks + 2) * 16 + 8);
            }
        }

        // bias + relu into regs (A still live in smem until now; barrier above
        // guarantees all warps' A reads are done before we overwrite below)
        #pragma unroll
        for (int j = 0; j < 16; j++) {
            int n = nb + j * 8 + tig * 2;
            h1v[j][0] = fmaxf(c[j][0] + b1f_s[n],     0.f);
            h1v[j][1] = fmaxf(c[j][1] + b1f_s[n + 1], 0.f);
            h1v[j][2] = fmaxf(c[j][2] + b1f_s[n],     0.f);
            h1v[j][3] = fmaxf(c[j][3] + b1f_s[n + 1], 0.f);
        }
    }
    __syncthreads();   // everyone done reading A_s; safe to overwrite with H1

    {
        const int mb = (wid >> 1) * 16;
        const int nb = (wid & 1) * 128;
        #pragma unroll
        for (int j = 0; j < 16; j++) {
            int n = nb + j * 8 + tig * 2;
            __nv_bfloat162 plo = __floats2bfloat162_rn(h1v[j][0], h1v[j][1]);
            __nv_bfloat162 phi = __floats2bfloat162_rn(h1v[j][2], h1v[j][3]);
            H1w[(mb + g)     * H1W + (n >> 1)] = *(uint32_t*)&plo;
            H1w[(mb + g + 8) * H1W + (n >> 1)] = *(uint32_t*)&phi;
        }
    }
    __syncthreads();

    // =========================== GEMM2 + W3 ===========================
    // C[64x128] = H1[64x256] @ W2t^T.  8 warps = 4 m-strips x 2 n-strips(64).
    {
        const int mb = (wid >> 1) * 16;
        const int nb = (wid & 1) * 64;
        float c[8][4];
        #pragma unroll
        for (int j = 0; j < 8; j++)
            #pragma unroll
            for (int q = 0; q < 4; q++) c[j][q] = 0.f;

        const int sn = t >> 1, sh = t & 1;   // 2 threads per weight row
        {
            uint4 w = *(const uint4*)(g_W2t + sn * HH1 + sh * 8);
            *(uint4*)((char*)Stw + sn * 48 + sh * 16) = w;
        }
        __syncthreads();
        uint4 pf = *(const uint4*)(g_W2t + sn * HH1 + 16 + sh * 8);

        for (int ks = 0; ks < NS2; ks++) {
            const uint32_t* buf = Stw + (ks & 1) * 3072;
            const int k0w = ks * 8;
            uint32_t a0 = H1w[(mb + g)     * H1W + k0w + tig];
            uint32_t a1 = H1w[(mb + g + 8) * H1W + k0w + tig];
            uint32_t a2 = H1w[(mb + g)     * H1W + k0w + 4 + tig];
            uint32_t a3 = H1w[(mb + g + 8) * H1W + k0w + 4 + tig];
            #pragma unroll
            for (int j = 0; j < 8; j++) {
                int n = nb + j * 8 + g;
                uint32_t b0 = buf[n * STW + tig];
                uint32_t b1 = buf[n * STW + 4 + tig];
                mma_bf16(c[j], a0, a1, a2, a3, b0, b1);
            }
            if (ks + 1 < NS2)
                *(uint4*)((char*)Stw + ((ks + 1) & 1) * 12288 + sn * 48 + sh * 16) = pf;
            __syncthreads();
            if (ks + 2 < NS2)
                pf = *(const uint4*)(g_W2t + sn * HH1 + (ks + 2) * 16 + sh * 8);
        }

        // epilogue: bias + relu, dot with W3, reduce over tig lanes
        float s_lo = 0.f, s_hi = 0.f;
        #pragma unroll
        for (int j = 0; j < 8; j++) {
            int n = nb + j * 8 + tig * 2;
            s_lo += fmaxf(c[j][0] + b2f_s[n],     0.f) * w3_s[n]
                  + fmaxf(c[j][1] + b2f_s[n + 1], 0.f) * w3_s[n + 1];
            s_hi += fmaxf(c[j][2] + b2f_s[n],     0.f) * w3_s[n]
                  + fmaxf(c[j][3] + b2f_s[n + 1], 0.f) * w3_s[n + 1];
        }
        s_lo += __shfl_xor_sync(0xffffffffu, s_lo, 1);
        s_lo += __shfl_xor_sync(0xffffffffu, s_lo, 2);
        s_hi += __shfl_xor_sync(0xffffffffu, s_hi, 1);
        s_hi += __shfl_xor_sync(0xffffffffu, s_hi, 2);
        if (tig == 0) {
            lg_s[(mb + g)     * 2 + (wid & 1)] = s_lo;
            lg_s[(mb + g + 8) * 2 + (wid & 1)] = s_hi;
        }
    }
    __syncthreads();

    if (t < BM) {
        float logit = lg_s[t * 2] + lg_s[t * 2 + 1] + fm_s[t] + b3[0];
        out[m0 + t] = 1.0f / (1.0f + expf(-logit));
    }
}

extern "C" void kernel_launch(void* const* d_in, const int* in_sizes, int n_in,
                              void* d_out, int out_size)
{
    const int*   X    = (const int*)  d_in[0];
    const float* emb1 = (const float*)d_in[1];
    const float* emb2 = (const float*)d_in[2];
    const float* W1   = (const float*)d_in[3];
    const float* b1   = (const float*)d_in[4];
    const float* g1   = (const float*)d_in[5];
    const float* be1  = (const float*)d_in[6];
    const float* m1   = (const float*)d_in[7];
    const float* v1   = (const float*)d_in[8];
    const float* W2   = (const float*)d_in[9];
    const float* b2   = (const float*)d_in[10];
    const float* g2   = (const float*)d_in[11];
    const float* be2  = (const float*)d_in[12];
    const float* m2   = (const float*)d_in[13];
    const float* v2   = (const float*)d_in[14];
    const float* W3   = (const float*)d_in[15];
    const float* b3   = (const float*)d_in[16];
    float* out = (float*)d_out;

    cudaFuncSetAttribute(deepfm_main_kernel,
                         cudaFuncAttributeMaxDynamicSharedMemorySize, SMEM_BYTES);

    deepfm_fold_kernel<<<272, 512>>>(W1, b1, g1, be1, m1, v1,
                                     W2, b2, g2, be2, m2, v2);
    deepfm_main_kernel<<<BB / BM, TPB, SMEM_BYTES>>>(X, emb1, emb2, W3, b3, out);
}

// round 10
// speedup vs baseline: 1.2533x; 1.2533x over previous
#include <cuda_runtime.h>
#include <cuda_bf16.h>
#include <math.h>
#include <stdint.h>

// DeepFM fused, bf16 mma.sync + cp.async weight pipeline. BM=128.
#define BB   16384
#define FF   26
#define VV   100000
#define DD   16
#define K1   416
#define HH1  256
#define HH2  128
#define EPSV 1e-5f

#define BM   128
#define TPB  512
#define NC1  13        // 416/32 k-chunks GEMM1
#define NC2  8         // 256/32 k-chunks GEMM2

#define AW   212       // A row pad (words); 20g+tig mod 32 conflict-free
#define H1W  132       // H1 row pad (words)
#define STW  20        // stage row words (80 B): 16 data + 4 pad
#define STBUF_B (256 * STW * 4)     // 20480 B per buffer

__device__ __nv_bfloat16 g_W1t[HH1 * K1];   // [n=256][k=416]
__device__ __nv_bfloat16 g_W2t[HH2 * HH1];  // [n=128][k=256]
__device__ float g_b1f[HH1];
__device__ float g_b2f[HH2];

__global__ void deepfm_fold_kernel(
    const float* __restrict__ W1, const float* __restrict__ b1,
    const float* __restrict__ g1, const float* __restrict__ be1,
    const float* __restrict__ m1, const float* __restrict__ v1,
    const float* __restrict__ W2, const float* __restrict__ b2,
    const float* __restrict__ g2, const float* __restrict__ be2,
    const float* __restrict__ m2, const float* __restrict__ v2)
{
    int i = blockIdx.x * blockDim.x + threadIdx.x;
    const int N1 = HH1 * K1, N2 = HH2 * HH1;
    for (int idx = i; idx < N1 + N2; idx += gridDim.x * blockDim.x) {
        if (idx < N1) {
            int n = idx / K1, k = idx - n * K1;
            float sc = g1[n] * rsqrtf(v1[n] + EPSV);
            g_W1t[idx] = __float2bfloat16_rn(W1[k * HH1 + n] * sc);
        } else {
            int t2 = idx - N1;
            int n = t2 >> 8, k = t2 & 255;
            float sc = g2[n] * rsqrtf(v2[n] + EPSV);
            g_W2t[t2] = __float2bfloat16_rn(W2[k * HH2 + n] * sc);
        }
    }
    if (i < HH1) {
        float sc = g1[i] * rsqrtf(v1[i] + EPSV);
        g_b1f[i] = be1[i] + (b1[i] - m1[i]) * sc;
    }
    if (i < HH2) {
        float sc = g2[i] * rsqrtf(v2[i] + EPSV);
        g_b2f[i] = be2[i] + (b2[i] - m2[i]) * sc;
    }
}

// smem layout (H1 aliases A)
#define OFF_A    0                       // 128*212*4 = 108544
#define OFF_ST   108544                  // 3 * 20480 = 61440
#define OFF_B1F  (OFF_ST + 3 * STBUF_B)  // 1024
#define OFF_B2F  (OFF_B1F + 1024)
#define OFF_W3   (OFF_B2F + 512)
#define OFF_FM   (OFF_W3 + 512)
#define OFF_LG   (OFF_FM + 512)
#define SMEM_BYTES (OFF_LG + 1024)       // 173568

__device__ __forceinline__ void mma_bf16(float c[4], uint32_t a0, uint32_t a1,
                                         uint32_t a2, uint32_t a3,
                                         uint32_t b0, uint32_t b1)
{
    asm volatile(
        "mma.sync.aligned.m16n8k16.row.col.f32.bf16.bf16.f32 "
        "{%0,%1,%2,%3}, {%4,%5,%6,%7}, {%8,%9}, {%0,%1,%2,%3};"
        : "+f"(c[0]), "+f"(c[1]), "+f"(c[2]), "+f"(c[3])
        : "r"(a0), "r"(a1), "r"(a2), "r"(a3), "r"(b0), "r"(b1));
}

__device__ __forceinline__ void cp16(uint32_t dst_smem, const void* src) {
    asm volatile("cp.async.cg.shared.global [%0], [%1], 16;\n"
                 :: "r"(dst_smem), "l"(src));
}
__device__ __forceinline__ void cp_commit() {
    asm volatile("cp.async.commit_group;\n" ::: "memory");
}
template <int N>
__device__ __forceinline__ void cp_wait() {
    asm volatile("cp.async.wait_group %0;\n" :: "n"(N) : "memory");
}

__global__ void __launch_bounds__(TPB, 1) deepfm_main_kernel(
    const int*   __restrict__ X,
    const float* __restrict__ emb1,
    const float* __restrict__ emb2,
    const float* __restrict__ W3,
    const float* __restrict__ b3,
    float*       __restrict__ out)
{
    extern __shared__ char smem[];
    uint32_t* Aw   = (uint32_t*)(smem + OFF_A);   // bf16x2 words, stride AW
    uint32_t* H1w  = Aw;                          // alias, stride H1W
    uint32_t* Stw  = (uint32_t*)(smem + OFF_ST);
    float* b1f_s = (float*)(smem + OFF_B1F);
    float* b2f_s = (float*)(smem + OFF_B2F);
    float* w3_s  = (float*)(smem + OFF_W3);
    float* fm_s  = (float*)(smem + OFF_FM);
    float* lg_s  = (float*)(smem + OFF_LG);
    const uint32_t st_base = (uint32_t)__cvta_generic_to_shared(Stw);

    const int t    = threadIdx.x;
    const int wid  = t >> 5;
    const int lane = t & 31;
    const int g    = lane >> 2;
    const int tig  = lane & 3;
    const int m0   = blockIdx.x * BM;

    // -------- cp.async stage W1 chunks 0,1 (overlaps with gather) --------
    // chunk ch -> buf ch%3. 1024 segs of 16B per chunk; thread does 2.
    {
        #pragma unroll
        for (int ch = 0; ch < 2; ch++) {
            #pragma unroll
            for (int i = 0; i < 2; i++) {
                int idx = t + i * TPB;
                int n = idx >> 2, seg = idx & 3;
                cp16(st_base + ch * STBUF_B + n * 80 + seg * 16,
                     (const char*)g_W1t + n * (K1 * 2) + ch * 64 + seg * 16);
            }
            cp_commit();
        }
    }

    // ---- stage small vectors ----
    if (t < HH1)                  b1f_s[t]       = g_b1f[t];
    else if (t < HH1 + HH2)       b2f_s[t - HH1] = g_b2f[t - HH1];
    else if (t < HH1 + 2 * HH2)   w3_s[t - HH1 - HH2] = W3[t - HH1 - HH2];

    // ---- gather embeddings -> bf16 A_s [m][k] ----
    for (int r = t; r < FF * BM; r += TPB) {
        int m = r & (BM - 1);
        int f = r >> 7;
        int idx = X[(m0 + m) * FF + f];
        const float4* src = (const float4*)(emb2 + ((long)f * VV + idx) * DD);
        float4 v0 = src[0], v1 = src[1], v2 = src[2], v3 = src[3];
        uint32_t* dst = Aw + m * AW + f * 8;
        __nv_bfloat162 p;
        p = __floats2bfloat162_rn(v0.x, v0.y); dst[0] = *(uint32_t*)&p;
        p = __floats2bfloat162_rn(v0.z, v0.w); dst[1] = *(uint32_t*)&p;
        p = __floats2bfloat162_rn(v1.x, v1.y); dst[2] = *(uint32_t*)&p;
        p = __floats2bfloat162_rn(v1.z, v1.w); dst[3] = *(uint32_t*)&p;
        p = __floats2bfloat162_rn(v2.x, v2.y); dst[4] = *(uint32_t*)&p;
        p = __floats2bfloat162_rn(v2.z, v2.w); dst[5] = *(uint32_t*)&p;
        p = __floats2bfloat162_rn(v3.x, v3.y); dst[6] = *(uint32_t*)&p;
        p = __floats2bfloat162_rn(v3.z, v3.w); dst[7] = *(uint32_t*)&p;
    }
    __syncthreads();

    // ---- FM: 4 threads per sample (d-quarters), shfl reduce ----
    {
        int q = t & 3, m = t >> 2;          // m 0..127, q 0..3
        const uint32_t* row = Aw + m * AW;
        float s[4] = {0,0,0,0}, ss[4] = {0,0,0,0};
        #pragma unroll
        for (int f = 0; f < FF; f++) {
            uint32_t u0 = row[f * 8 + 2 * q];
            uint32_t u1 = row[f * 8 + 2 * q + 1];
            __nv_bfloat162 p0 = *(__nv_bfloat162*)&u0;
            __nv_bfloat162 p1 = *(__nv_bfloat162*)&u1;
            float x0 = __low2float(p0), x1 = __high2float(p0);
            float x2 = __low2float(p1), x3 = __high2float(p1);
            s[0] += x0; ss[0] += x0 * x0;
            s[1] += x1; ss[1] += x1 * x1;
            s[2] += x2; ss[2] += x2 * x2;
            s[3] += x3; ss[3] += x3 * x3;
        }
        float part = 0.f;
        #pragma unroll
        for (int d = 0; d < 4; d++) part += s[d] * s[d] - ss[d];
        part *= 0.5f;
        int f_lo = q * 7, f_hi = (q == 3) ? FF : f_lo + 7;
        for (int f = f_lo; f < f_hi; f++)
            part += emb1[f * VV + X[(m0 + m) * FF + f]];
        part += __shfl_xor_sync(0xffffffffu, part, 1);
        part += __shfl_xor_sync(0xffffffffu, part, 2);
        if (q == 0) fm_s[m] = part;
    }

    // =========================== GEMM1 ===========================
    // C[128x256] = A @ W1t^T. 16 warps = 8 m-strips(16) x 2 n-strips(128).
    float h1v[16][4];
    {
        const int mb = (wid >> 1) * 16;
        const int nb = (wid & 1) * 128;
        float c[16][4];
        #pragma unroll
        for (int j = 0; j < 16; j++)
            #pragma unroll
            for (int q = 0; q < 4; q++) c[j][q] = 0.f;

        for (int ch = 0; ch < NC1; ch++) {
            if (ch < NC1 - 2) cp_wait<1>(); else cp_wait<0>();
            __syncthreads();
            // issue chunk ch+2 (buffer (ch+2)%3: its readers finished iter ch-1)
            if (ch + 2 < NC1) {
                #pragma unroll
                for (int i = 0; i < 2; i++) {
                    int idx = t + i * TPB;
                    int n = idx >> 2, seg = idx & 3;
                    cp16(st_base + ((ch + 2) % 3) * STBUF_B + n * 80 + seg * 16,
                         (const char*)g_W1t + n * (K1 * 2) + (ch + 2) * 64 + seg * 16);
                }
                cp_commit();
            }
            const uint32_t* buf = Stw + (ch % 3) * (STBUF_B / 4);
            #pragma unroll
            for (int ksub = 0; ksub < 2; ksub++) {
                const int k0w = ch * 16 + ksub * 8;
                uint32_t a0 = Aw[(mb + g)     * AW + k0w + tig];
                uint32_t a1 = Aw[(mb + g + 8) * AW + k0w + tig];
                uint32_t a2 = Aw[(mb + g)     * AW + k0w + 4 + tig];
                uint32_t a3 = Aw[(mb + g + 8) * AW + k0w + 4 + tig];
                #pragma unroll
                for (int j = 0; j < 16; j++) {
                    int n = nb + j * 8 + g;
                    uint32_t b0 = buf[n * STW + ksub * 8 + tig];
                    uint32_t b1 = buf[n * STW + ksub * 8 + 4 + tig];
                    mma_bf16(c[j], a0, a1, a2, a3, b0, b1);
                }
            }
        }

        // stage W2 chunks 0,1 (overlaps epilogue). W2 chunk c -> buf (c+1)%3.
        // buf1/buf2 last read at GEMM1 iters 10/11 -> all warps past iter-12
        // barrier, so done.
        #pragma unroll
        for (int c2 = 0; c2 < 2; c2++) {
            int idx = t;                       // 512 segs
            int n = idx >> 2, seg = idx & 3;
            cp16(st_base + ((c2 + 1) % 3) * STBUF_B + n * 80 + seg * 16,
                 (const char*)g_W2t + n * (HH1 * 2) + c2 * 64 + seg * 16);
            cp_commit();
        }

        #pragma unroll
        for (int j = 0; j < 16; j++) {
            int n = nb + j * 8 + tig * 2;
            h1v[j][0] = fmaxf(c[j][0] + b1f_s[n],     0.f);
            h1v[j][1] = fmaxf(c[j][1] + b1f_s[n + 1], 0.f);
            h1v[j][2] = fmaxf(c[j][2] + b1f_s[n],     0.f);
            h1v[j][3] = fmaxf(c[j][3] + b1f_s[n + 1], 0.f);
        }
    }
    __syncthreads();   // all A reads done -> safe to overwrite with H1

    {
        const int mb = (wid >> 1) * 16;
        const int nb = (wid & 1) * 128;
        #pragma unroll
        for (int j = 0; j < 16; j++) {
            int n = nb + j * 8 + tig * 2;
            __nv_bfloat162 plo = __floats2bfloat162_rn(h1v[j][0], h1v[j][1]);
            __nv_bfloat162 phi = __floats2bfloat162_rn(h1v[j][2], h1v[j][3]);
            H1w[(mb + g)     * H1W + (n >> 1)] = *(uint32_t*)&plo;
            H1w[(mb + g + 8) * H1W + (n >> 1)] = *(uint32_t*)&phi;
        }
    }

    // =========================== GEMM2 + W3 ===========================
    // C[128x128] = H1 @ W2t^T. chunk c lives in buf (c+1)%3.
    {
        const int mb = (wid >> 1) * 16;
        const int nb = (wid & 1) * 64;
        float c[8][4];
        #pragma unroll
        for (int j = 0; j < 8; j++)
            #pragma unroll
            for (int q = 0; q < 4; q++) c[j][q] = 0.f;

        for (int ch = 0; ch < NC2; ch++) {
            if (ch < NC2 - 2) cp_wait<1>(); else cp_wait<0>();
            __syncthreads();   // ch=0: also fences H1 stores above
            if (ch + 2 < NC2) {
                int idx = t;
                int n = idx >> 2, seg = idx & 3;
                cp16(st_base + ((ch + 3) % 3) * STBUF_B + n * 80 + seg * 16,
                     (const char*)g_W2t + n * (HH1 * 2) + (ch + 2) * 64 + seg * 16);
                cp_commit();
            }
            const uint32_t* buf = Stw + ((ch + 1) % 3) * (STBUF_B / 4);
            #pragma unroll
            for (int ksub = 0; ksub < 2; ksub++) {
                const int k0w = ch * 16 + ksub * 8;
                uint32_t a0 = H1w[(mb + g)     * H1W + k0w + tig];
                uint32_t a1 = H1w[(mb + g + 8) * H1W + k0w + tig];
                uint32_t a2 = H1w[(mb + g)     * H1W + k0w + 4 + tig];
                uint32_t a3 = H1w[(mb + g + 8) * H1W + k0w + 4 + tig];
                #pragma unroll
                for (int j = 0; j < 8; j++) {
                    int n = nb + j * 8 + g;
                    uint32_t b0 = buf[n * STW + ksub * 8 + tig];
                    uint32_t b1 = buf[n * STW + ksub * 8 + 4 + tig];
                    mma_bf16(c[j], a0, a1, a2, a3, b0, b1);
                }
            }
        }

        float s_lo = 0.f, s_hi = 0.f;
        #pragma unroll
        for (int j = 0; j < 8; j++) {
            int n = nb + j * 8 + tig * 2;
            s_lo += fmaxf(c[j][0] + b2f_s[n],     0.f) * w3_s[n]
                  + fmaxf(c[j][1] + b2f_s[n + 1], 0.f) * w3_s[n + 1];
            s_hi += fmaxf(c[j][2] + b2f_s[n],     0.f) * w3_s[n]
                  + fmaxf(c[j][3] + b2f_s[n + 1], 0.f) * w3_s[n + 1];
        }
        s_lo += __shfl_xor_sync(0xffffffffu, s_lo, 1);
        s_lo += __shfl_xor_sync(0xffffffffu, s_lo, 2);
        s_hi += __shfl_xor_sync(0xffffffffu, s_hi, 1);
        s_hi += __shfl_xor_sync(0xffffffffu, s_hi, 2);
        if (tig == 0) {
            lg_s[(mb + g)     * 2 + (wid & 1)] = s_lo;
            lg_s[(mb + g + 8) * 2 + (wid & 1)] = s_hi;
        }
    }
    __syncthreads();

    if (t < BM) {
        float logit = lg_s[t * 2] + lg_s[t * 2 + 1] + fm_s[t] + b3[0];
        out[m0 + t] = 1.0f / (1.0f + expf(-logit));
    }
}

extern "C" void kernel_launch(void* const* d_in, const int* in_sizes, int n_in,
                              void* d_out, int out_size)
{
    const int*   X    = (const int*)  d_in[0];
    const float* emb1 = (const float*)d_in[1];
    const float* emb2 = (const float*)d_in[2];
    const float* W1   = (const float*)d_in[3];
    const float* b1   = (const float*)d_in[4];
    const float* g1   = (const float*)d_in[5];
    const float* be1  = (const float*)d_in[6];
    const float* m1   = (const float*)d_in[7];
    const float* v1   = (const float*)d_in[8];
    const float* W2   = (const float*)d_in[9];
    const float* b2   = (const float*)d_in[10];
    const float* g2   = (const float*)d_in[11];
    const float* be2  = (const float*)d_in[12];
    const float* m2   = (const float*)d_in[13];
    const float* v2   = (const float*)d_in[14];
    const float* W3   = (const float*)d_in[15];
    const float* b3   = (const float*)d_in[16];
    float* out = (float*)d_out;

    cudaFuncSetAttribute(deepfm_main_kernel,
                         cudaFuncAttributeMaxDynamicSharedMemorySize, SMEM_BYTES);

    deepfm_fold_kernel<<<272, 512>>>(W1, b1, g1, be1, m1, v1,
                                     W2, b2, g2, be2, m2, v2);
    deepfm_main_kernel<<<BB / BM, TPB, SMEM_BYTES>>>(X, emb1, emb2, W3, b3, out);
}